// round 5
// baseline (speedup 1.0000x reference)
#include <cuda_runtime.h>
#include <math.h>

#define NN     100000
#define EE_MAX 3400000
#define HD     16
#define FIN    767
#define NC     10
#define EPSV   1e-12f

// ---------------- scratch ---------------------------------------------------
__device__ float g_hn  [NN * HD];   // normalized h
__device__ float g_nrm1[NN];        // max(||h||, eps)
__device__ float g_x1n [NN * HD];   // normalized x1
__device__ float g_nrm2[NN];        // max(||x1||, eps)
__device__ int   g_deg [NN];
__device__ int   g_rowptr[NN + 1];
__device__ int   g_cursor[NN];
__device__ int   g_csrc[EE_MAX];
__device__ int   g_aux[256];

// ---------------- f32x2 helpers ---------------------------------------------
__device__ __forceinline__ unsigned long long pk2(float lo, float hi) {
    unsigned long long r;
    asm("mov.b64 %0, {%1,%2};" : "=l"(r) : "f"(lo), "f"(hi));
    return r;
}
__device__ __forceinline__ void upk2(unsigned long long v, float& lo, float& hi) {
    asm("mov.b64 {%0,%1}, %2;" : "=f"(lo), "=f"(hi) : "l"(v));
}
__device__ __forceinline__ unsigned long long ffma2(unsigned long long a,
                                                    unsigned long long b,
                                                    unsigned long long c) {
    unsigned long long d;
    asm("fma.rn.f32x2 %0, %1, %2, %3;" : "=l"(d) : "l"(a), "l"(b), "l"(c));
    return d;
}
__device__ __forceinline__ unsigned long long fadd2(unsigned long long a,
                                                    unsigned long long b) {
    unsigned long long d;
    asm("add.rn.f32x2 %0, %1, %2;" : "=l"(d) : "l"(a), "l"(b));
    return d;
}

// ---------------- CSR build --------------------------------------------------
__global__ void k_count(const int* __restrict__ ei, int E, int n) {
    int idx = blockIdx.x * blockDim.x + threadIdx.x;
    if (idx < E) atomicAdd(&g_deg[__ldg(&ei[E + idx])], 1);
    else if (idx < E + n) atomicAdd(&g_deg[idx - E], 1);
}

__global__ void k_scan_chunk(int n) {
    __shared__ int wsums[16];
    int tid = threadIdx.x, lane = tid & 31, w = tid >> 5;
    int gid = blockIdx.x * 512 + tid;
    int v = (gid < n) ? g_deg[gid] : 0;
    int s = v;
#pragma unroll
    for (int off = 1; off < 32; off <<= 1) {
        int t = __shfl_up_sync(0xffffffffu, s, off);
        if (lane >= off) s += t;
    }
    if (lane == 31) wsums[w] = s;
    __syncthreads();
    int add = 0;
#pragma unroll
    for (int i = 0; i < 16; i++) add += (i < w) ? wsums[i] : 0;
    s += add;
    if (gid < n) g_rowptr[gid + 1] = s;
    if (tid == 511) g_aux[blockIdx.x] = s;
}

__global__ void k_scan_aux(int nb) {
    int tid = threadIdx.x, lane = tid & 31, w = tid >> 5;
    int v = (tid < nb) ? g_aux[tid] : 0;
    int s = v;
#pragma unroll
    for (int off = 1; off < 32; off <<= 1) {
        int t = __shfl_up_sync(0xffffffffu, s, off);
        if (lane >= off) s += t;
    }
    __shared__ int wsum[8];
    if (lane == 31) wsum[w] = s;
    __syncthreads();
    int add = 0;
#pragma unroll
    for (int i = 0; i < 8; i++) add += (i < w) ? wsum[i] : 0;
    if (tid < nb) g_aux[tid] = s - v + add;   // exclusive
}

__global__ void k_scan_add(int n) {
    int gid = blockIdx.x * 512 + threadIdx.x;
    if (gid < n) {
        int v = g_rowptr[gid + 1] + g_aux[blockIdx.x];
        g_rowptr[gid + 1] = v;
        if (gid + 1 < n) g_cursor[gid + 1] = v;
    }
    if (gid == 0) { g_rowptr[0] = 0; g_cursor[0] = 0; }
}

__global__ void k_scatter(const int* __restrict__ ei, int E, int n) {
    int idx = blockIdx.x * blockDim.x + threadIdx.x;
    int total = E + n;
    if (idx >= total) return;
    int src, dst;
    if (idx < E) { src = __ldg(&ei[idx]); dst = __ldg(&ei[E + idx]); }
    else         { src = idx - E; dst = src; }
    int pos = atomicAdd(&g_cursor[dst], 1);
    g_csrc[pos] = src;
}

// ---------------- lin1: 8 rows/warp, 2-way k-split, f32x2 --------------------
// lane = (kg, jlane): kg = lane>>4 (2 k-groups of 4 kp), jlane = lane&15.
// acc[r*4+q] = f32x2 outputs (k, k+1), k = 2*(kg*4+q).
// smem quad (jp,kp): [w[2kp][2jp], w[2kp+1][2jp], w[2kp][2jp+1], w[2kp+1][2jp+1]]
// float offset = jp*36 + kp*4  (144B stride -> conflict-free LDS.128)
#define LIN1_SMEM_BYTES (384 * 36 * 4)   // 55296
__global__ __launch_bounds__(256, 2) void k_lin1(const float* __restrict__ x,
                                                 const float* __restrict__ w,
                                                 const float* __restrict__ b,
                                                 float* __restrict__ hn,
                                                 float* __restrict__ nrm,
                                                 int n) {
    extern __shared__ float wf[];
    for (int q = threadIdx.x; q < 384 * 8; q += 256) {
        int jp = q >> 3, kp = q & 7;
        int j = 2 * jp, k = 2 * kp;
        float f0 = w[k * FIN + j];
        float f1 = w[(k + 1) * FIN + j];
        float f2 = (j + 1 < FIN) ? w[k * FIN + j + 1] : 0.f;
        float f3 = (j + 1 < FIN) ? w[(k + 1) * FIN + j + 1] : 0.f;
        *(float4*)(wf + jp * 36 + kp * 4) = make_float4(f0, f1, f2, f3);
    }
    __syncthreads();

    int warp = threadIdx.x >> 5, lane = threadIdx.x & 31;
    int jlane = lane & 15, kg = lane >> 4;
    int rowBase = (blockIdx.x * 8 + warp) * 8;
    if (rowBase >= n) return;
    bool lastWarp = (rowBase + 8 >= n);

    unsigned long long acc[32];
#pragma unroll
    for (int i = 0; i < 32; i++) acc[i] = 0ull;

    const float* x0 = x + (size_t)rowBase * FIN;
    const float* wb = wf + kg * 16;   // kp base offset (kg*4 quads)

    float lo[8], hi[8];
    {
        int j = 2 * jlane;
#pragma unroll
        for (int r = 0; r < 8; r++) {
            const float* xr = x0 + r * FIN;
            lo[r] = xr[j];
            hi[r] = xr[j + 1];
        }
    }

    for (int it = 0; it < 24; ++it) {
        int jp = jlane + it * 16;
        float nlo[8], nhi[8];
        if (it + 1 < 24) {
            int jpn = jp + 16;
            int j = 2 * jpn;
            // jpn==383 (lastWarp, r==7) would read x[n*FIN]: clamp offset; the
            // staged weight for that slot is 0 so any finite value is fine.
            int ho = (lastWarp && jpn == 383) ? 0 : 1;
#pragma unroll
            for (int r = 0; r < 8; r++) {
                const float* xr = x0 + r * FIN;
                nlo[r] = xr[j];
                nhi[r] = xr[j + ((r == 7) ? ho : 1)];
            }
        }
        const float* wj = wb + jp * 36;
        ulonglong2 q0 = *(const ulonglong2*)(wj);
        ulonglong2 q1 = *(const ulonglong2*)(wj + 4);
        ulonglong2 q2 = *(const ulonglong2*)(wj + 8);
        ulonglong2 q3 = *(const ulonglong2*)(wj + 12);
#pragma unroll
        for (int r = 0; r < 8; r++) {
            unsigned long long blo = pk2(lo[r], lo[r]);
            unsigned long long bhi = pk2(hi[r], hi[r]);
            unsigned long long a0 = acc[r * 4 + 0];
            unsigned long long a1 = acc[r * 4 + 1];
            unsigned long long a2 = acc[r * 4 + 2];
            unsigned long long a3 = acc[r * 4 + 3];
            a0 = ffma2(blo, q0.x, a0); a0 = ffma2(bhi, q0.y, a0);
            a1 = ffma2(blo, q1.x, a1); a1 = ffma2(bhi, q1.y, a1);
            a2 = ffma2(blo, q2.x, a2); a2 = ffma2(bhi, q2.y, a2);
            a3 = ffma2(blo, q3.x, a3); a3 = ffma2(bhi, q3.y, a3);
            acc[r * 4 + 0] = a0;
            acc[r * 4 + 1] = a1;
            acc[r * 4 + 2] = a2;
            acc[r * 4 + 3] = a3;
        }
        if (it + 1 < 24) {
#pragma unroll
            for (int r = 0; r < 8; r++) { lo[r] = nlo[r]; hi[r] = nhi[r]; }
        }
    }

    // halving butterfly over the 16-lane j-group
#define REDSTEP(OFF, HALF)                                                     \
    {                                                                          \
        bool up = (lane & OFF) != 0;                                           \
        _Pragma("unroll")                                                      \
        for (int i = 0; i < HALF; i++) {                                       \
            unsigned long long send = up ? acc[i] : acc[i + HALF];             \
            unsigned long long recv = __shfl_xor_sync(0xffffffffu, send, OFF); \
            unsigned long long keep = up ? acc[i + HALF] : acc[i];             \
            acc[i] = fadd2(keep, recv);                                        \
        }                                                                      \
    }
    REDSTEP(1, 16)
    REDSTEP(2, 8)
    REDSTEP(4, 4)
    REDSTEP(8, 2)
#undef REDSTEP

    // lane owns row r = 4*b0+2*b1+b2 (bits of jlane), cols colb..colb+3
    int b0 = jlane & 1, b1 = (jlane >> 1) & 1, b2 = (jlane >> 2) & 1;
    int b3 = (jlane >> 3) & 1;
    int r    = 4 * b0 + 2 * b1 + b2;
    int colb = kg * 8 + 4 * b3;
    int row  = rowBase + r;

    float4 bb = __ldg((const float4*)b + (colb >> 2));
    float h0, h1, h2, h3;
    upk2(acc[0], h0, h1);
    upk2(acc[1], h2, h3);
    h0 = fmaxf(h0 + bb.x, 0.f);
    h1 = fmaxf(h1 + bb.y, 0.f);
    h2 = fmaxf(h2 + bb.z, 0.f);
    h3 = fmaxf(h3 + bb.w, 0.f);
    float ss = h0 * h0 + h1 * h1 + h2 * h2 + h3 * h3;
    ss += __shfl_xor_sync(0xffffffffu, ss, 8);
    ss += __shfl_xor_sync(0xffffffffu, ss, 16);
    float nr  = fmaxf(sqrtf(ss), EPSV);
    float inv = 1.f / nr;
    *(float4*)(hn + (size_t)row * HD + colb) =
        make_float4(h0 * inv, h1 * inv, h2 * inv, h3 * inv);
    if (colb == 0) nrm[row] = nr;
}

// ---------------- AGNN conv (warp/node, quad/edge, pipelined) ----------------
template <int MODE>
__global__ __launch_bounds__(256) void k_conv(const float* __restrict__ featn,
                                              const float* __restrict__ nrm,
                                              const float* __restrict__ beta_ptr,
                                              float* __restrict__ out,
                                              float* __restrict__ outn,
                                              float* __restrict__ nrmout,
                                              const float* __restrict__ w2,
                                              const float* __restrict__ b2,
                                              int n) {
    __shared__ float ws[NC * HD + NC];
    if (MODE == 1) {
        if (threadIdx.x < NC * HD) ws[threadIdx.x] = w2[threadIdx.x];
        if (threadIdx.x < NC)      ws[NC * HD + threadIdx.x] = b2[threadIdx.x];
        __syncthreads();
    }

    int gw    = (blockIdx.x * blockDim.x + threadIdx.x) >> 5;
    int lane  = threadIdx.x & 31;
    if (gw >= n) return;
    int chunk = lane & 3;
    int slot  = lane >> 2;

    float beta = (MODE == 1) ? __ldg(beta_ptr) : 1.0f;
    float ab   = fabsf(beta);

    const float4* fn4 = (const float4*)featn;
    float4 q = fn4[(size_t)gw * 4 + chunk];
    q.x *= beta; q.y *= beta; q.z *= beta; q.w *= beta;

    int start = g_rowptr[gw], end = g_rowptr[gw + 1];
    int nit = (end - start + 7) >> 3;

    float ssum = 0.f;
    float4 acc = make_float4(0.f, 0.f, 0.f, 0.f);

    int e = start + slot;
    bool valid = (e < end);
    int s = valid ? __ldg(&g_csrc[e]) : 0;

    for (int it = 0; it < nit; ++it) {
        int  en = e + 8;
        bool vn = (en < end);
        int  sn = vn ? __ldg(&g_csrc[en]) : 0;
        float nv = __ldg(&nrm[s]);
        float4 v = fn4[(size_t)s * 4 + chunk];
        float d = v.x*q.x + v.y*q.y + v.z*q.z + v.w*q.w;
        d += __shfl_xor_sync(0xffffffffu, d, 1);
        d += __shfl_xor_sync(0xffffffffu, d, 2);
        float ex  = valid ? __expf(d - ab) : 0.f;
        float exn = ex * nv;
        ssum += ex;
        acc.x += exn * v.x; acc.y += exn * v.y;
        acc.z += exn * v.z; acc.w += exn * v.w;
        e = en; s = sn; valid = vn;
    }

#pragma unroll
    for (int off = 4; off <= 16; off <<= 1) {
        ssum  += __shfl_xor_sync(0xffffffffu, ssum,  off);
        acc.x += __shfl_xor_sync(0xffffffffu, acc.x, off);
        acc.y += __shfl_xor_sync(0xffffffffu, acc.y, off);
        acc.z += __shfl_xor_sync(0xffffffffu, acc.z, off);
        acc.w += __shfl_xor_sync(0xffffffffu, acc.w, off);
    }
    float inv = 1.f / ssum;
    float4 o = make_float4(acc.x*inv, acc.y*inv, acc.z*inv, acc.w*inv);

    if (MODE == 0) {
        float ss = o.x*o.x + o.y*o.y + o.z*o.z + o.w*o.w;
        ss += __shfl_xor_sync(0xffffffffu, ss, 1);
        ss += __shfl_xor_sync(0xffffffffu, ss, 2);
        float nr   = fmaxf(sqrtf(ss), EPSV);
        float invn = 1.f / nr;
        if (slot == 0) {
            ((float4*)out )[(size_t)gw * 4 + chunk] = o;
            ((float4*)outn)[(size_t)gw * 4 + chunk] =
                make_float4(o.x*invn, o.y*invn, o.z*invn, o.w*invn);
            if (lane == 0) nrmout[gw] = nr;
        }
    } else {
        float z[NC];
#pragma unroll
        for (int c = 0; c < NC; c++) {
            const float* wc = ws + c * HD + chunk * 4;
            z[c] = o.x*wc[0] + o.y*wc[1] + o.z*wc[2] + o.w*wc[3];
        }
#pragma unroll
        for (int off = 1; off <= 2; off <<= 1)
#pragma unroll
            for (int c = 0; c < NC; c++)
                z[c] += __shfl_xor_sync(0xffffffffu, z[c], off);
#pragma unroll
        for (int c = 0; c < NC; c++) z[c] += ws[NC * HD + c];
        float mx = z[0];
#pragma unroll
        for (int c = 1; c < NC; c++) mx = fmaxf(mx, z[c]);
        float se = 0.f;
#pragma unroll
        for (int c = 0; c < NC; c++) se += __expf(z[c] - mx);
        float lse = mx + __logf(se);
        if (lane < NC) out[(size_t)gw * NC + lane] = z[lane] - lse;
    }
}

// ---------------- launch -----------------------------------------------------
extern "C" void kernel_launch(void* const* d_in, const int* in_sizes, int n_in,
                              void* d_out, int out_size) {
    const float* x    = (const float*)d_in[0];
    const int*   ei   = (const int*)  d_in[1];
    const float* w1   = (const float*)d_in[2];
    const float* b1   = (const float*)d_in[3];
    const float* bet2 = (const float*)d_in[4];
    const float* w2   = (const float*)d_in[5];
    const float* b2   = (const float*)d_in[6];
    float* out = (float*)d_out;

    int n = NN;
    int E = in_sizes[1] / 2;

    float* x1 = out + (size_t)n * NC;   // x1 output lives in d_out tail

    float* p_hn;  cudaGetSymbolAddress((void**)&p_hn,  g_hn);
    float* p_n1;  cudaGetSymbolAddress((void**)&p_n1,  g_nrm1);
    float* p_x1n; cudaGetSymbolAddress((void**)&p_x1n, g_x1n);
    float* p_n2;  cudaGetSymbolAddress((void**)&p_n2,  g_nrm2);
    int*   p_deg; cudaGetSymbolAddress((void**)&p_deg, g_deg);

    static cudaStream_t s2 = nullptr;
    static cudaEvent_t evFork = nullptr, evJoin = nullptr;
    if (!s2) {
        cudaStreamCreateWithFlags(&s2, cudaStreamNonBlocking);
        cudaEventCreateWithFlags(&evFork, cudaEventDisableTiming);
        cudaEventCreateWithFlags(&evJoin, cudaEventDisableTiming);
        cudaFuncSetAttribute(k_lin1, cudaFuncAttributeMaxDynamicSharedMemorySize,
                             LIN1_SMEM_BYTES);
    }

    const int T = 256;
    int nchunk = (n + 511) / 512;

    // ---- fork: CSR build on s2, lin1 on default stream ----
    cudaEventRecord(evFork, 0);
    cudaStreamWaitEvent(s2, evFork, 0);

    cudaMemsetAsync(p_deg, 0, n * sizeof(int), s2);
    k_count<<<(E + n + T - 1) / T, T, 0, s2>>>(ei, E, n);
    k_scan_chunk<<<nchunk, 512, 0, s2>>>(n);
    k_scan_aux<<<1, 256, 0, s2>>>(nchunk);

    k_lin1<<<(n + 63) / 64, 256, LIN1_SMEM_BYTES>>>(x, w1, b1, p_hn, p_n1, n);

    k_scan_add<<<nchunk, 512, 0, s2>>>(n);
    k_scatter<<<(E + n + T - 1) / T, T, 0, s2>>>(ei, E, n);

    // ---- join ----
    cudaEventRecord(evJoin, s2);
    cudaStreamWaitEvent(0, evJoin, 0);

    int convBlocks = (n * 32 + 255) / 256;
    k_conv<0><<<convBlocks, 256>>>(p_hn, p_n1, nullptr, x1, p_x1n, p_n2,
                                   nullptr, nullptr, n);
    k_conv<1><<<convBlocks, 256>>>(p_x1n, p_n2, bet2, out, nullptr, nullptr,
                                   w2, b2, n);
}